// round 5
// baseline (speedup 1.0000x reference)
#include <cuda_runtime.h>
#include <cuda_bf16.h>
#include <cstdint>

// CFConv fused via mma.sync tf32. Weight fragments live in a __device__ global
// (L1D-resident, read via __ldg) so smem/CTA is small -> 4 CTAs/SM.
// out[dst] += nw[src] * ( ssp(rbf @ W1 + b1) @ W2 + b2 )

static constexpr int TILE    = 128;
static constexpr int THREADS = 128;
static constexpr int STRIDE  = 68;

// shared: SBUF tile + biases
static constexpr int SBUF_OFF = 0;                   // 128*68 floats
static constexpr int B1_OFF   = TILE * STRIDE;       // 8704
static constexpr int B2_OFF   = B1_OFF + 64;
static constexpr int SMEM_FLOATS = B2_OFF + 64;      // 8832
static constexpr int SMEM_BYTES  = SMEM_FLOATS * 4;  // 35328

// fragment-packed weights (tf32), one-time init
__device__ float WF1g[4096];
__device__ float WF2g[4096];

__device__ __forceinline__ float to_tf32(float x) {
    float r;
    asm("cvt.rna.tf32.f32 %0, %1;" : "=f"(r) : "f"(x));
    return r;
}

__device__ __forceinline__ void mma8(float c[4], const uint32_t a[4], const uint32_t b[2]) {
    asm volatile(
        "mma.sync.aligned.m16n8k8.row.col.f32.tf32.tf32.f32 "
        "{%0,%1,%2,%3}, {%4,%5,%6,%7}, {%8,%9}, {%0,%1,%2,%3};"
        : "+f"(c[0]), "+f"(c[1]), "+f"(c[2]), "+f"(c[3])
        : "r"(a[0]), "r"(a[1]), "r"(a[2]), "r"(a[3]), "r"(b[0]), "r"(b[1]));
}

__device__ __forceinline__ float ssp(float x) {
    float h = 0.5f * x;
    if (h > 14.0f) return x;
    return 2.0f * __logf(1.0f + __expf(h));
}

__device__ __forceinline__ void red4(float* p, float a, float b, float c, float d) {
    asm volatile("red.global.add.v4.f32 [%0], {%1,%2,%3,%4};"
                 :: "l"(p), "f"(a), "f"(b), "f"(c), "f"(d) : "memory");
}

__device__ __forceinline__ void cp16(const float* s, const void* g) {
    uint32_t sa;
    asm("{.reg .u64 t; cvta.to.shared.u64 t, %1; cvt.u32.u64 %0, t;}" : "=r"(sa) : "l"(s));
    asm volatile("cp.async.cg.shared.global [%0], [%1], 16;" :: "r"(sa), "l"(g));
}

// acc[mt][j][4] += tile(S rows warp*32..+32) @ WF (fragment-packed, global/L1)
__device__ __forceinline__ void gemm64(const float* __restrict__ S,
                                       const float* __restrict__ WF,
                                       float acc[2][8][4], int warp, int lane) {
    const int r = lane >> 2, c = lane & 3;
    const float* wf = WF + lane * 2;
#pragma unroll
    for (int s = 0; s < 8; s++) {
        uint32_t a[2][4];
#pragma unroll
        for (int mt = 0; mt < 2; mt++) {
            const float* base = S + (warp * 32 + mt * 16 + r) * STRIDE + s * 8 + c;
            a[mt][0] = __float_as_uint(to_tf32(base[0]));
            a[mt][1] = __float_as_uint(to_tf32(base[8 * STRIDE]));
            a[mt][2] = __float_as_uint(to_tf32(base[4]));
            a[mt][3] = __float_as_uint(to_tf32(base[8 * STRIDE + 4]));
        }
#pragma unroll
        for (int j = 0; j < 8; j++) {
            const float2 bv = __ldg((const float2*)(wf + (s * 8 + j) * 64));
            uint32_t b[2] = {__float_as_uint(bv.x), __float_as_uint(bv.y)};
            mma8(acc[0][j], a[0], b);
            mma8(acc[1][j], a[1], b);
        }
    }
}

__global__ void __launch_bounds__(THREADS, 4)
cfconv_kernel(const float* __restrict__ nw,
              const float* __restrict__ rbf,
              const float* __restrict__ b1,
              const float* __restrict__ b2,
              const int*   __restrict__ src,
              const int*   __restrict__ dst,
              float* __restrict__ out,
              int E) {
    extern __shared__ __align__(16) float sm[];
    float* SBUF = sm + SBUF_OFF;
    float* B1S  = sm + B1_OFF;
    float* B2S  = sm + B2_OFF;

    const int tid  = threadIdx.x;
    const int warp = tid >> 5;
    const int lane = tid & 31;
    const int r = lane >> 2, c = lane & 3;

    if (tid < 64) { B1S[tid] = b1[tid]; B2S[tid] = b2[tid]; }
    __syncthreads();

    const int ntiles = (E + TILE - 1) / TILE;

    for (int t = blockIdx.x; t < ntiles; t += gridDim.x) {
        const int et = t * TILE;

        // ---- stage rbf tile [128 x 64] -> SBUF ----
#pragma unroll
        for (int i = 0; i < 16; i++) {
            int g = tid + i * THREADS;
            int row = g >> 4, q = g & 15;
            int e = et + row;
            float* d = &SBUF[row * STRIDE + q * 4];
            if (e < E) cp16(d, rbf + (long)e * 64 + q * 4);
            else       *(float4*)d = make_float4(0.f, 0.f, 0.f, 0.f);
        }
        asm volatile("cp.async.commit_group;" ::: "memory");
        asm volatile("cp.async.wait_group 0;" ::: "memory");
        __syncthreads();

        // ---- GEMM1 ----
        float acc[2][8][4];
#pragma unroll
        for (int mt = 0; mt < 2; mt++)
#pragma unroll
            for (int j = 0; j < 8; j++)
#pragma unroll
                for (int p = 0; p < 4; p++) acc[mt][j][p] = 0.f;
        gemm64(SBUF, WF1g, acc, warp, lane);
        __syncthreads();

        // ---- hidden = ssp(acc + b1) -> SBUF ----
#pragma unroll
        for (int mt = 0; mt < 2; mt++) {
            int row0 = warp * 32 + mt * 16 + r;
#pragma unroll
            for (int j = 0; j < 8; j++) {
                int col = j * 8 + 2 * c;
                float2 bb = *(float2*)&B1S[col];
                *(float2*)&SBUF[row0 * STRIDE + col] =
                    make_float2(ssp(acc[mt][j][0] + bb.x), ssp(acc[mt][j][1] + bb.y));
                *(float2*)&SBUF[(row0 + 8) * STRIDE + col] =
                    make_float2(ssp(acc[mt][j][2] + bb.x), ssp(acc[mt][j][3] + bb.y));
            }
        }
        __syncthreads();

        // ---- GEMM2 ----
#pragma unroll
        for (int mt = 0; mt < 2; mt++)
#pragma unroll
            for (int j = 0; j < 8; j++)
#pragma unroll
                for (int p = 0; p < 4; p++) acc[mt][j][p] = 0.f;
        gemm64(SBUF, WF2g, acc, warp, lane);
        __syncthreads();

        // ---- filter = acc + b2 -> SBUF ----
#pragma unroll
        for (int mt = 0; mt < 2; mt++) {
            int row0 = warp * 32 + mt * 16 + r;
#pragma unroll
            for (int j = 0; j < 8; j++) {
                int col = j * 8 + 2 * c;
                float2 bb = *(float2*)&B2S[col];
                *(float2*)&SBUF[row0 * STRIDE + col] =
                    make_float2(acc[mt][j][0] + bb.x, acc[mt][j][1] + bb.y);
                *(float2*)&SBUF[(row0 + 8) * STRIDE + col] =
                    make_float2(acc[mt][j][2] + bb.x, acc[mt][j][3] + bb.y);
            }
        }
        __syncthreads();

        // ---- epilogue: one edge per thread ----
        const int e = et + tid;
        if (e < E) {
            const int sN = src[e];
            const int dN = dst[e];
            const float4* nr = (const float4*)(nw + (long)sN * 64);
            float* ob = out + (long)dN * 64;
            const float* rw = &SBUF[tid * STRIDE];
#pragma unroll
            for (int q = 0; q < 16; q++) {
                float4 cv = *(const float4*)&rw[q * 4];
                float4 nv = __ldg(nr + q);
                red4(ob + q * 4, cv.x * nv.x, cv.y * nv.y, cv.z * nv.z, cv.w * nv.w);
            }
        }
        __syncthreads();
    }
}

// one-time: pack W1,W2 into per-thread fragment order (tf32)
__global__ void pack_kernel(const float* __restrict__ W1, const float* __restrict__ W2) {
    int f = blockIdx.x * blockDim.x + threadIdx.x;
    if (f < 4096) {
        int s = f >> 9, j = (f >> 6) & 7, t = (f >> 1) & 31, h = f & 1;
        int k = s * 8 + (t & 3) + h * 4;
        int n = j * 8 + (t >> 2);
        WF1g[f] = to_tf32(W1[k * 64 + n]);
        WF2g[f] = to_tf32(W2[k * 64 + n]);
    }
}

__global__ void zero_kernel(float4* __restrict__ o, int n4) {
    int i = blockIdx.x * blockDim.x + threadIdx.x;
    if (i < n4) o[i] = make_float4(0.f, 0.f, 0.f, 0.f);
}

extern "C" void kernel_launch(void* const* d_in, const int* in_sizes, int n_in,
                              void* d_out, int out_size) {
    const float* nw  = (const float*)d_in[0];
    const float* rbf = (const float*)d_in[1];
    const float* W1  = (const float*)d_in[2];
    const float* b1  = (const float*)d_in[3];
    const float* W2  = (const float*)d_in[4];
    const float* b2  = (const float*)d_in[5];
    const int*   src = (const int*)d_in[6];
    const int*   dst = (const int*)d_in[7];
    float* out = (float*)d_out;

    const int E = in_sizes[1] / 64;

    int n4 = out_size / 4;
    zero_kernel<<<(n4 + 255) / 256, 256>>>((float4*)out, n4);
    pack_kernel<<<32, 128>>>(W1, W2);
    cfconv_kernel<<<592, THREADS, SMEM_BYTES>>>(nw, rbf, b1, b2, src, dst, out, E);
}

// round 6
// speedup vs baseline: 1.7923x; 1.7923x over previous
#include <cuda_runtime.h>
#include <cuda_bf16.h>
#include <cstdint>

// CFConv fused via mma.sync tf32, warp-autonomous tiles + software pipelining.
// out[dst] += nw[src] * ( ssp(rbf @ W1 + b1) @ W2 + b2 )
// Each warp owns 32 edges end-to-end: stage(cp.async) -> GEMM1 -> ssp -> GEMM2
// -> register epilogue (red.v2). No CTA-wide barriers in the main loop.

static constexpr int TILE    = 128;   // edges per CTA-tile (32 per warp)
static constexpr int THREADS = 128;
static constexpr int STRIDE  = 68;    // conflict-free row stride (floats)

// shared layout (floats)
static constexpr int SBUF_OFF = 0;                    // 128 x 68
static constexpr int W1F_OFF  = TILE * STRIDE;        // 8704, fragment-packed
static constexpr int W2F_OFF  = W1F_OFF + 4096;       // 12800
static constexpr int SMEM_FLOATS = W2F_OFF + 4096;    // 16896
static constexpr int SMEM_BYTES  = SMEM_FLOATS * 4;   // 67584

__device__ __forceinline__ float to_tf32(float x) {
    float r;
    asm("cvt.rna.tf32.f32 %0, %1;" : "=f"(r) : "f"(x));
    return r;
}

__device__ __forceinline__ void mma8(float c[4], const uint32_t a[4],
                                     uint32_t b0, uint32_t b1) {
    asm volatile(
        "mma.sync.aligned.m16n8k8.row.col.f32.tf32.tf32.f32 "
        "{%0,%1,%2,%3}, {%4,%5,%6,%7}, {%8,%9}, {%0,%1,%2,%3};"
        : "+f"(c[0]), "+f"(c[1]), "+f"(c[2]), "+f"(c[3])
        : "r"(a[0]), "r"(a[1]), "r"(a[2]), "r"(a[3]), "r"(b0), "r"(b1));
}

__device__ __forceinline__ float ssp(float x) {
    float h = 0.5f * x;
    if (h > 14.0f) return x;
    return 2.0f * __logf(1.0f + __expf(h));
}

__device__ __forceinline__ void red2(float* p, float a, float b) {
    asm volatile("red.global.add.v2.f32 [%0], {%1,%2};"
                 :: "l"(p), "f"(a), "f"(b) : "memory");
}

__device__ __forceinline__ void cp16(const float* s, const void* g) {
    uint32_t sa;
    asm("{.reg .u64 t; cvta.to.shared.u64 t, %1; cvt.u32.u64 %0, t;}" : "=r"(sa) : "l"(s));
    asm volatile("cp.async.cg.shared.global [%0], [%1], 16;" :: "r"(sa), "l"(g));
}

// warp-local 32x64 @ 64x64 GEMM. B fragments packed for LDS.128 (2 j's per load).
__device__ __forceinline__ void gemm32(const float* __restrict__ S,
                                       const float* __restrict__ WF,
                                       float acc[2][8][4],
                                       int wb, int lane, int r, int c) {
#pragma unroll
    for (int s = 0; s < 8; s++) {
        uint32_t a[2][4];
#pragma unroll
        for (int mt = 0; mt < 2; mt++) {
            const float* base = S + (wb + mt * 16 + r) * STRIDE + s * 8 + c;
            a[mt][0] = __float_as_uint(to_tf32(base[0]));
            a[mt][1] = __float_as_uint(to_tf32(base[8 * STRIDE]));
            a[mt][2] = __float_as_uint(to_tf32(base[4]));
            a[mt][3] = __float_as_uint(to_tf32(base[8 * STRIDE + 4]));
        }
#pragma unroll
        for (int jp = 0; jp < 4; jp++) {
            float4 bv = *(const float4*)&WF[(((s * 4 + jp) * 32) + lane) * 4];
            uint32_t bx = __float_as_uint(bv.x), by = __float_as_uint(bv.y);
            uint32_t bz = __float_as_uint(bv.z), bw = __float_as_uint(bv.w);
            mma8(acc[0][2 * jp],     a[0], bx, by);
            mma8(acc[1][2 * jp],     a[1], bx, by);
            mma8(acc[0][2 * jp + 1], a[0], bz, bw);
            mma8(acc[1][2 * jp + 1], a[1], bz, bw);
        }
    }
}

__global__ void __launch_bounds__(THREADS, 3)
cfconv_kernel(const float* __restrict__ nw,
              const float* __restrict__ rbf,
              const float* __restrict__ W1,
              const float* __restrict__ b1,
              const float* __restrict__ W2,
              const float* __restrict__ b2,
              const int*   __restrict__ src,
              const int*   __restrict__ dst,
              float* __restrict__ out,
              int E) {
    extern __shared__ __align__(16) float sm[];
    float* SBUF = sm + SBUF_OFF;
    float* W1F  = sm + W1F_OFF;
    float* W2F  = sm + W2F_OFF;

    const int tid  = threadIdx.x;
    const int warp = tid >> 5;
    const int lane = tid & 31;
    const int r = lane >> 2, c = lane & 3;
    const int wb = warp * 32;

    // ---- one-time: pack weights into LDS.128-friendly fragment order ----
    // f: h=f&3, lane=(f>>2)&31, jp=(f>>7)&3, s=f>>9
    // j=2*jp+(h>>1); k=s*8+(lane&3)+(h&1)*4; n=j*8+(lane>>2)
    for (int f = tid; f < 4096; f += THREADS) {
        int h = f & 3, ln = (f >> 2) & 31, jp = (f >> 7) & 3, s = f >> 9;
        int j = 2 * jp + (h >> 1);
        int k = s * 8 + (ln & 3) + (h & 1) * 4;
        int n = j * 8 + (ln >> 2);
        W1F[f] = to_tf32(W1[k * 64 + n]);
        W2F[f] = to_tf32(W2[k * 64 + n]);
    }

    // biases -> registers (col j*8+2c .. +1)
    float2 bb1[8], bb2[8];
#pragma unroll
    for (int j = 0; j < 8; j++) {
        bb1[j] = __ldg((const float2*)(b1 + j * 8 + 2 * c));
        bb2[j] = __ldg((const float2*)(b2 + j * 8 + 2 * c));
    }
    __syncthreads();   // weights ready

    const int ntiles = (E + TILE - 1) / TILE;
    float* wsbuf = SBUF + wb * STRIDE;   // this warp's 32-row slice

    // ---- stage first tile (warp-local) ----
    int t = blockIdx.x;
    if (t < ntiles) {
        const int et = t * TILE + wb;
#pragma unroll
        for (int i = 0; i < 16; i++) {
            int g = lane + i * 32;
            int row = g >> 4, q = g & 15;
            int e = et + row;
            float* d = &wsbuf[row * STRIDE + q * 4];
            if (e < E) cp16(d, rbf + (long)e * 64 + q * 4);
            else       *(float4*)d = make_float4(0.f, 0.f, 0.f, 0.f);
        }
        asm volatile("cp.async.commit_group;" ::: "memory");
    }

    for (; t < ntiles; t += gridDim.x) {
        const int et = t * TILE + wb;    // this warp's first edge

        // src/dst for this warp's 32 edges (in flight during GEMMs)
        int myE = et + lane;
        int se = (myE < E) ? __ldg(src + myE) : 0;
        int de = (myE < E) ? __ldg(dst + myE) : 0;

        asm volatile("cp.async.wait_group 0;" ::: "memory");
        __syncwarp();

        // ---- GEMM1 ----
        float acc[2][8][4];
#pragma unroll
        for (int mt = 0; mt < 2; mt++)
#pragma unroll
            for (int j = 0; j < 8; j++)
#pragma unroll
                for (int p = 0; p < 4; p++) acc[mt][j][p] = 0.f;
        gemm32(SBUF, W1F, acc, wb, lane, r, c);
        __syncwarp();

        // ---- hidden = ssp(acc + b1) -> warp SBUF slice ----
#pragma unroll
        for (int mt = 0; mt < 2; mt++) {
            int row0 = wb + mt * 16 + r;
#pragma unroll
            for (int j = 0; j < 8; j++) {
                int col = j * 8 + 2 * c;
                *(float2*)&SBUF[row0 * STRIDE + col] =
                    make_float2(ssp(acc[mt][j][0] + bb1[j].x), ssp(acc[mt][j][1] + bb1[j].y));
                *(float2*)&SBUF[(row0 + 8) * STRIDE + col] =
                    make_float2(ssp(acc[mt][j][2] + bb1[j].x), ssp(acc[mt][j][3] + bb1[j].y));
            }
        }
        __syncwarp();

        // ---- GEMM2 ----
#pragma unroll
        for (int mt = 0; mt < 2; mt++)
#pragma unroll
            for (int j = 0; j < 8; j++)
#pragma unroll
                for (int p = 0; p < 4; p++) acc[mt][j][p] = 0.f;
        gemm32(SBUF, W2F, acc, wb, lane, r, c);
        __syncwarp();

        // ---- SBUF slice free: stage NEXT tile now (overlaps epilogue) ----
        int tn = t + gridDim.x;
        if (tn < ntiles) {
            const int etn = tn * TILE + wb;
#pragma unroll
            for (int i = 0; i < 16; i++) {
                int g = lane + i * 32;
                int row = g >> 4, q = g & 15;
                int e = etn + row;
                float* d = &wsbuf[row * STRIDE + q * 4];
                if (e < E) cp16(d, rbf + (long)e * 64 + q * 4);
                else       *(float4*)d = make_float4(0.f, 0.f, 0.f, 0.f);
            }
            asm volatile("cp.async.commit_group;" ::: "memory");
        }

        // ---- epilogue straight from registers ----
#pragma unroll
        for (int mt = 0; mt < 2; mt++) {
#pragma unroll
            for (int rr = 0; rr < 2; rr++) {
                int x = mt * 16 + rr * 8 + r;                 // row within warp tile
                int sN = __shfl_sync(0xffffffff, se, x);
                int dN = __shfl_sync(0xffffffff, de, x);
                if (et + x < E) {
                    const float* nr = nw + (long)sN * 64;
                    float* ob = out + (long)dN * 64;
#pragma unroll
                    for (int j = 0; j < 8; j++) {
                        int col = j * 8 + 2 * c;
                        float2 nv = __ldg((const float2*)(nr + col));
                        red2(ob + col,
                             nv.x * (acc[mt][j][rr * 2 + 0] + bb2[j].x),
                             nv.y * (acc[mt][j][rr * 2 + 1] + bb2[j].y));
                    }
                }
            }
        }
    }
}

__global__ void zero_kernel(float4* __restrict__ o, int n4) {
    int i = blockIdx.x * blockDim.x + threadIdx.x;
    if (i < n4) o[i] = make_float4(0.f, 0.f, 0.f, 0.f);
}

extern "C" void kernel_launch(void* const* d_in, const int* in_sizes, int n_in,
                              void* d_out, int out_size) {
    const float* nw  = (const float*)d_in[0];
    const float* rbf = (const float*)d_in[1];
    const float* W1  = (const float*)d_in[2];
    const float* b1  = (const float*)d_in[3];
    const float* W2  = (const float*)d_in[4];
    const float* b2  = (const float*)d_in[5];
    const int*   src = (const int*)d_in[6];
    const int*   dst = (const int*)d_in[7];
    float* out = (float*)d_out;

    const int E = in_sizes[1] / 64;

    cudaFuncSetAttribute(cfconv_kernel,
                         cudaFuncAttributeMaxDynamicSharedMemorySize, SMEM_BYTES);

    int n4 = out_size / 4;
    zero_kernel<<<(n4 + 255) / 256, 256>>>((float4*)out, n4);

    cfconv_kernel<<<444, THREADS, SMEM_BYTES>>>(nw, rbf, W1, b1, W2, b2, src, dst, out, E);
}

// round 7
// speedup vs baseline: 1.9690x; 1.0986x over previous
#include <cuda_runtime.h>
#include <cuda_bf16.h>
#include <cstdint>

// CFConv fused via mma.sync tf32. 256-thread CTAs (8 warp-autonomous 32-edge
// slices sharing one weight copy) -> 2 CTAs/SM = 16 warps/SM.
// out[dst] += nw[src] * ( ssp(rbf @ W1 + b1) @ W2 + b2 )

static constexpr int TILE    = 256;   // edges per CTA-tile (32 per warp)
static constexpr int THREADS = 256;
static constexpr int STRIDE  = 68;

// shared layout (floats)
static constexpr int SBUF_OFF = 0;                    // 256 x 68
static constexpr int W1F_OFF  = TILE * STRIDE;        // 17408
static constexpr int W2F_OFF  = W1F_OFF + 4096;       // 21504
static constexpr int B1_OFF   = W2F_OFF + 4096;       // 25600
static constexpr int B2_OFF   = B1_OFF + 64;          // 25664
static constexpr int SMEM_FLOATS = B2_OFF + 64;       // 25728
static constexpr int SMEM_BYTES  = SMEM_FLOATS * 4;   // 102912

__device__ __forceinline__ float to_tf32(float x) {
    float r;
    asm("cvt.rna.tf32.f32 %0, %1;" : "=f"(r) : "f"(x));
    return r;
}

__device__ __forceinline__ void mma8(float c[4], const uint32_t a[4],
                                     uint32_t b0, uint32_t b1) {
    asm volatile(
        "mma.sync.aligned.m16n8k8.row.col.f32.tf32.tf32.f32 "
        "{%0,%1,%2,%3}, {%4,%5,%6,%7}, {%8,%9}, {%0,%1,%2,%3};"
        : "+f"(c[0]), "+f"(c[1]), "+f"(c[2]), "+f"(c[3])
        : "r"(a[0]), "r"(a[1]), "r"(a[2]), "r"(a[3]), "r"(b0), "r"(b1));
}

__device__ __forceinline__ float ssp(float x) {
    float h = 0.5f * x;
    if (h > 14.0f) return x;
    return 2.0f * __logf(1.0f + __expf(h));
}

__device__ __forceinline__ void red2(float* p, float a, float b) {
    asm volatile("red.global.add.v2.f32 [%0], {%1,%2};"
                 :: "l"(p), "f"(a), "f"(b) : "memory");
}

__device__ __forceinline__ void cp16(const float* s, const void* g) {
    uint32_t sa;
    asm("{.reg .u64 t; cvta.to.shared.u64 t, %1; cvt.u32.u64 %0, t;}" : "=r"(sa) : "l"(s));
    asm volatile("cp.async.cg.shared.global [%0], [%1], 16;" :: "r"(sa), "l"(g));
}

// warp-local 32x64 @ 64x64 GEMM; A fed as raw fp32 bits (hw tf32 truncation),
// B fragment-packed for LDS.128 (2 n-tiles per load).
__device__ __forceinline__ void gemm32(const float* __restrict__ S,
                                       const float* __restrict__ WF,
                                       float acc[2][8][4],
                                       int wb, int lane, int r, int c) {
#pragma unroll
    for (int s = 0; s < 8; s++) {
        uint32_t a[2][4];
#pragma unroll
        for (int mt = 0; mt < 2; mt++) {
            const float* base = S + (wb + mt * 16 + r) * STRIDE + s * 8 + c;
            a[mt][0] = __float_as_uint(base[0]);
            a[mt][1] = __float_as_uint(base[8 * STRIDE]);
            a[mt][2] = __float_as_uint(base[4]);
            a[mt][3] = __float_as_uint(base[8 * STRIDE + 4]);
        }
#pragma unroll
        for (int jp = 0; jp < 4; jp++) {
            float4 bv = *(const float4*)&WF[(((s * 4 + jp) * 32) + lane) * 4];
            uint32_t bx = __float_as_uint(bv.x), by = __float_as_uint(bv.y);
            uint32_t bz = __float_as_uint(bv.z), bw = __float_as_uint(bv.w);
            mma8(acc[0][2 * jp],     a[0], bx, by);
            mma8(acc[1][2 * jp],     a[1], bx, by);
            mma8(acc[0][2 * jp + 1], a[0], bz, bw);
            mma8(acc[1][2 * jp + 1], a[1], bz, bw);
        }
    }
}

__global__ void __launch_bounds__(THREADS, 2)
cfconv_kernel(const float* __restrict__ nw,
              const float* __restrict__ rbf,
              const float* __restrict__ W1,
              const float* __restrict__ b1,
              const float* __restrict__ W2,
              const float* __restrict__ b2,
              const int*   __restrict__ src,
              const int*   __restrict__ dst,
              float* __restrict__ out,
              int E) {
    extern __shared__ __align__(16) float sm[];
    float* SBUF = sm + SBUF_OFF;
    float* W1F  = sm + W1F_OFF;
    float* W2F  = sm + W2F_OFF;
    float* B1S  = sm + B1_OFF;
    float* B2S  = sm + B2_OFF;

    const int tid  = threadIdx.x;
    const int warp = tid >> 5;
    const int lane = tid & 31;
    const int r = lane >> 2, c = lane & 3;
    const int wb = warp * 32;

    // ---- one-time: pack weights (rna tf32) into LDS.128 fragment order ----
    for (int f = tid; f < 4096; f += THREADS) {
        int h = f & 3, ln = (f >> 2) & 31, jp = (f >> 7) & 3, s = f >> 9;
        int j = 2 * jp + (h >> 1);
        int k = s * 8 + (ln & 3) + (h & 1) * 4;
        int n = j * 8 + (ln >> 2);
        W1F[f] = to_tf32(W1[k * 64 + n]);
        W2F[f] = to_tf32(W2[k * 64 + n]);
    }
    if (tid < 64) { B1S[tid] = b1[tid]; B2S[tid] = b2[tid]; }
    __syncthreads();

    const int ntiles = (E + TILE - 1) / TILE;
    float* wsbuf = SBUF + wb * STRIDE;

    // ---- stage first tile (warp-local) ----
    int t = blockIdx.x;
    if (t < ntiles) {
        const int et = t * TILE + wb;
#pragma unroll
        for (int i = 0; i < 16; i++) {
            int g = lane + i * 32;
            int row = g >> 4, q = g & 15;
            int e = et + row;
            float* d = &wsbuf[row * STRIDE + q * 4];
            if (e < E) cp16(d, rbf + (long)e * 64 + q * 4);
            else       *(float4*)d = make_float4(0.f, 0.f, 0.f, 0.f);
        }
        asm volatile("cp.async.commit_group;" ::: "memory");
    }

    for (; t < ntiles; t += gridDim.x) {
        const int et = t * TILE + wb;

        int myE = et + lane;
        int se = (myE < E) ? __ldg(src + myE) : 0;
        int de = (myE < E) ? __ldg(dst + myE) : 0;

        asm volatile("cp.async.wait_group 0;" ::: "memory");
        __syncwarp();

        // ---- GEMM1 ----
        float acc[2][8][4];
#pragma unroll
        for (int mt = 0; mt < 2; mt++)
#pragma unroll
            for (int j = 0; j < 8; j++)
#pragma unroll
                for (int p = 0; p < 4; p++) acc[mt][j][p] = 0.f;
        gemm32(SBUF, W1F, acc, wb, lane, r, c);
        __syncwarp();

        // ---- hidden = ssp(acc + b1) -> warp SBUF slice ----
#pragma unroll
        for (int mt = 0; mt < 2; mt++) {
            int row0 = wb + mt * 16 + r;
#pragma unroll
            for (int j = 0; j < 8; j++) {
                int col = j * 8 + 2 * c;
                float2 bb = *(const float2*)&B1S[col];
                *(float2*)&SBUF[row0 * STRIDE + col] =
                    make_float2(ssp(acc[mt][j][0] + bb.x), ssp(acc[mt][j][1] + bb.y));
                *(float2*)&SBUF[(row0 + 8) * STRIDE + col] =
                    make_float2(ssp(acc[mt][j][2] + bb.x), ssp(acc[mt][j][3] + bb.y));
            }
        }
        __syncwarp();

        // ---- GEMM2 ----
#pragma unroll
        for (int mt = 0; mt < 2; mt++)
#pragma unroll
            for (int j = 0; j < 8; j++)
#pragma unroll
                for (int p = 0; p < 4; p++) acc[mt][j][p] = 0.f;
        gemm32(SBUF, W2F, acc, wb, lane, r, c);
        __syncwarp();

        // ---- SBUF slice free: stage NEXT tile (overlaps epilogue) ----
        int tn = t + gridDim.x;
        if (tn < ntiles) {
            const int etn = tn * TILE + wb;
#pragma unroll
            for (int i = 0; i < 16; i++) {
                int g = lane + i * 32;
                int row = g >> 4, q = g & 15;
                int e = etn + row;
                float* d = &wsbuf[row * STRIDE + q * 4];
                if (e < E) cp16(d, rbf + (long)e * 64 + q * 4);
                else       *(float4*)d = make_float4(0.f, 0.f, 0.f, 0.f);
            }
            asm volatile("cp.async.commit_group;" ::: "memory");
        }

        // ---- epilogue from registers ----
#pragma unroll
        for (int mt = 0; mt < 2; mt++) {
#pragma unroll
            for (int rr = 0; rr < 2; rr++) {
                int x = mt * 16 + rr * 8 + r;
                int sN = __shfl_sync(0xffffffff, se, x);
                int dN = __shfl_sync(0xffffffff, de, x);
                if (et + x < E) {
                    const float* nr = nw + (long)sN * 64;
                    float* ob = out + (long)dN * 64;
#pragma unroll
                    for (int j = 0; j < 8; j++) {
                        int col = j * 8 + 2 * c;
                        float2 bb = *(const float2*)&B2S[col];
                        float2 nv = __ldg((const float2*)(nr + col));
                        red2(ob + col,
                             nv.x * (acc[mt][j][rr * 2 + 0] + bb.x),
                             nv.y * (acc[mt][j][rr * 2 + 1] + bb.y));
                    }
                }
            }
        }
    }
}

__global__ void zero_kernel(float4* __restrict__ o, int n4) {
    int i = blockIdx.x * blockDim.x + threadIdx.x;
    if (i < n4) o[i] = make_float4(0.f, 0.f, 0.f, 0.f);
}

extern "C" void kernel_launch(void* const* d_in, const int* in_sizes, int n_in,
                              void* d_out, int out_size) {
    const float* nw  = (const float*)d_in[0];
    const float* rbf = (const float*)d_in[1];
    const float* W1  = (const float*)d_in[2];
    const float* b1  = (const float*)d_in[3];
    const float* W2  = (const float*)d_in[4];
    const float* b2  = (const float*)d_in[5];
    const int*   src = (const int*)d_in[6];
    const int*   dst = (const int*)d_in[7];
    float* out = (float*)d_out;

    const int E = in_sizes[1] / 64;

    cudaFuncSetAttribute(cfconv_kernel,
                         cudaFuncAttributeMaxDynamicSharedMemorySize, SMEM_BYTES);

    int n4 = out_size / 4;
    zero_kernel<<<(n4 + 255) / 256, 256>>>((float4*)out, n4);

    cfconv_kernel<<<296, THREADS, SMEM_BYTES>>>(nw, rbf, W1, b1, W2, b2, src, dst, out, E);
}

// round 9
// speedup vs baseline: 2.3460x; 1.1914x over previous
#include <cuda_runtime.h>
#include <cuda_fp16.h>
#include <cstdint>

// CFConv fused via mma.sync fp16 (m16n8k16, fp32 accum). 256-thr CTAs, 8
// warp-autonomous 32-edge slices; hidden stored fp16 overlaying the warp's
// SBUF slice. out[dst] += nw[src] * ( ssp(rbf @ W1 + b1) @ W2 + b2 )

static constexpr int TILE    = 256;
static constexpr int THREADS = 256;
static constexpr int STRIDE  = 72;    // fp32 row stride (conflict-free LDS.64)

// shared layout (floats)
static constexpr int SBUF_OFF = 0;                    // 256 x 72 fp32
static constexpr int W1F_OFF  = TILE * STRIDE;        // 18432: 512 uint4 (fp16 frags)
static constexpr int W2F_OFF  = W1F_OFF + 2048;       // 20480
static constexpr int B1_OFF   = W2F_OFF + 2048;       // 22528
static constexpr int B2_OFF   = B1_OFF + 64;          // 22592
static constexpr int SMEM_FLOATS = B2_OFF + 64;       // 22656
static constexpr int SMEM_BYTES  = SMEM_FLOATS * 4;   // 90624

__device__ __forceinline__ uint32_t h2(float lo, float hi) {
    uint32_t d;   // first PTX src -> upper half
    asm("cvt.rn.f16x2.f32 %0, %1, %2;" : "=r"(d) : "f"(hi), "f"(lo));
    return d;
}
__device__ __forceinline__ uint32_t h2f2(float2 p) { return h2(p.x, p.y); }

__device__ __forceinline__ void mma16(float c[4], const uint32_t a[4],
                                      uint32_t b0, uint32_t b1) {
    asm volatile(
        "mma.sync.aligned.m16n8k16.row.col.f32.f16.f16.f32 "
        "{%0,%1,%2,%3}, {%4,%5,%6,%7}, {%8,%9}, {%0,%1,%2,%3};"
        : "+f"(c[0]), "+f"(c[1]), "+f"(c[2]), "+f"(c[3])
        : "r"(a[0]), "r"(a[1]), "r"(a[2]), "r"(a[3]), "r"(b0), "r"(b1));
}

__device__ __forceinline__ float ssp(float x) {
    float h = 0.5f * x;
    if (h > 14.0f) return x;
    return 2.0f * __logf(1.0f + __expf(h));
}

__device__ __forceinline__ void red2(float* p, float a, float b) {
    asm volatile("red.global.add.v2.f32 [%0], {%1,%2};"
                 :: "l"(p), "f"(a), "f"(b) : "memory");
}

__device__ __forceinline__ void cp16(const float* s, const void* g) {
    uint32_t sa;
    asm("{.reg .u64 t; cvta.to.shared.u64 t, %1; cvt.u32.u64 %0, t;}" : "=r"(sa) : "l"(s));
    asm volatile("cp.async.cg.shared.global [%0], [%1], 16;" :: "r"(sa), "l"(g));
}

__global__ void __launch_bounds__(THREADS, 2)
cfconv_kernel(const float* __restrict__ nw,
              const float* __restrict__ rbf,
              const float* __restrict__ W1,
              const float* __restrict__ b1,
              const float* __restrict__ W2,
              const float* __restrict__ b2,
              const int*   __restrict__ src,
              const int*   __restrict__ dst,
              float* __restrict__ out,
              int E) {
    extern __shared__ __align__(16) float sm[];
    float* SBUF = sm + SBUF_OFF;
    uint4* W1F  = (uint4*)(sm + W1F_OFF);
    uint4* W2F  = (uint4*)(sm + W2F_OFF);
    float* B1S  = sm + B1_OFF;
    float* B2S  = sm + B2_OFF;

    const int tid  = threadIdx.x;
    const int warp = tid >> 5;
    const int lane = tid & 31;
    const int r = lane >> 2, c = lane & 3;
    const int wb = warp * 32;

    // ---- one-time: pack W1,W2 as fp16 B-fragments (LDS.128 order) ----
    // element g = s*4+jp (s=k/16, jp=j/2), lane: 8 halves =
    //   j=2jp : (k0,n0),(k0+1,n0),(k0+8,n0),(k0+9,n0)
    //   j=2jp+1: same with n0+8 ;  k0 = s*16+2c, n0 = jp*16+r
    for (int idx = tid; idx < 512; idx += THREADS) {
        int g = idx >> 5, ln = idx & 31;
        int s = g >> 2, jp = g & 3;
        int rr = ln >> 2, cc = ln & 3;
        int k0 = s * 16 + 2 * cc;
        int n0 = jp * 16 + rr;
        const float* Ws[2] = {W1, W2};
        uint4* Fs[2] = {W1F, W2F};
#pragma unroll
        for (int w = 0; w < 2; w++) {
            const float* W = Ws[w];
            uint4 v;
            v.x = h2(W[k0 * 64 + n0],       W[(k0 + 1) * 64 + n0]);
            v.y = h2(W[(k0 + 8) * 64 + n0], W[(k0 + 9) * 64 + n0]);
            v.z = h2(W[k0 * 64 + n0 + 8],       W[(k0 + 1) * 64 + n0 + 8]);
            v.w = h2(W[(k0 + 8) * 64 + n0 + 8], W[(k0 + 9) * 64 + n0 + 8]);
            Fs[w][idx] = v;
        }
    }
    if (tid < 64) { B1S[tid] = b1[tid]; B2S[tid] = b2[tid]; }
    __syncthreads();

    const int ntiles = (E + TILE - 1) / TILE;
    float* wsbuf = SBUF + wb * STRIDE;              // warp's fp32 slice
    __half* H = (__half*)wsbuf;                     // fp16 overlay, stride 72 halves

    // ---- stage first tile ----
    int t = blockIdx.x;
    if (t < ntiles) {
        const int et = t * TILE + wb;
#pragma unroll
        for (int i = 0; i < 16; i++) {
            int g = lane + i * 32;
            int row = g >> 4, q = g & 15;
            int e = et + row;
            float* d = &wsbuf[row * STRIDE + q * 4];
            if (e < E) cp16(d, rbf + (long)e * 64 + q * 4);
            else       *(float4*)d = make_float4(0.f, 0.f, 0.f, 0.f);
        }
        asm volatile("cp.async.commit_group;" ::: "memory");
    }

    for (; t < ntiles; t += gridDim.x) {
        const int et = t * TILE + wb;

        int myE = et + lane;
        int se = (myE < E) ? __ldg(src + myE) : 0;
        int de = (myE < E) ? __ldg(dst + myE) : 0;

        asm volatile("cp.async.wait_group 0;" ::: "memory");
        __syncwarp();

        // ---- GEMM1: A = fp32 SBUF (cvt to fp16), B = W1F ----
        float acc[2][8][4];
#pragma unroll
        for (int mt = 0; mt < 2; mt++)
#pragma unroll
            for (int j = 0; j < 8; j++)
#pragma unroll
                for (int p = 0; p < 4; p++) acc[mt][j][p] = 0.f;

#pragma unroll
        for (int s = 0; s < 4; s++) {
            uint32_t a[2][4];
#pragma unroll
            for (int mt = 0; mt < 2; mt++) {
                const float* base = wsbuf + (mt * 16 + r) * STRIDE + s * 16 + 2 * c;
                a[mt][0] = h2f2(*(const float2*)(base));
                a[mt][1] = h2f2(*(const float2*)(base + 8 * STRIDE));
                a[mt][2] = h2f2(*(const float2*)(base + 8));
                a[mt][3] = h2f2(*(const float2*)(base + 8 * STRIDE + 8));
            }
#pragma unroll
            for (int jp = 0; jp < 4; jp++) {
                uint4 bv = W1F[(s * 4 + jp) * 32 + lane];
                mma16(acc[0][2 * jp],     a[0], bv.x, bv.y);
                mma16(acc[1][2 * jp],     a[1], bv.x, bv.y);
                mma16(acc[0][2 * jp + 1], a[0], bv.z, bv.w);
                mma16(acc[1][2 * jp + 1], a[1], bv.z, bv.w);
            }
        }
        __syncwarp();

        // ---- hidden = ssp(acc + b1) -> fp16 overlay of warp slice ----
#pragma unroll
        for (int mt = 0; mt < 2; mt++) {
#pragma unroll
            for (int j = 0; j < 8; j++) {
                int col = j * 8 + 2 * c;
                float2 bb = *(const float2*)&B1S[col];
                *(uint32_t*)&H[(mt * 16 + r) * STRIDE + col] =
                    h2(ssp(acc[mt][j][0] + bb.x), ssp(acc[mt][j][1] + bb.y));
                *(uint32_t*)&H[(mt * 16 + r + 8) * STRIDE + col] =
                    h2(ssp(acc[mt][j][2] + bb.x), ssp(acc[mt][j][3] + bb.y));
            }
        }
        __syncwarp();

        // ---- GEMM2: A = fp16 overlay, B = W2F ----
#pragma unroll
        for (int mt = 0; mt < 2; mt++)
#pragma unroll
            for (int j = 0; j < 8; j++)
#pragma unroll
                for (int p = 0; p < 4; p++) acc[mt][j][p] = 0.f;

#pragma unroll
        for (int s = 0; s < 4; s++) {
            uint32_t a[2][4];
#pragma unroll
            for (int mt = 0; mt < 2; mt++) {
                const __half* base = H + (mt * 16 + r) * STRIDE + s * 16 + 2 * c;
                a[mt][0] = *(const uint32_t*)(base);
                a[mt][1] = *(const uint32_t*)(base + 8 * STRIDE);
                a[mt][2] = *(const uint32_t*)(base + 8);
                a[mt][3] = *(const uint32_t*)(base + 8 * STRIDE + 8);
            }
#pragma unroll
            for (int jp = 0; jp < 4; jp++) {
                uint4 bv = W2F[(s * 4 + jp) * 32 + lane];
                mma16(acc[0][2 * jp],     a[0], bv.x, bv.y);
                mma16(acc[1][2 * jp],     a[1], bv.x, bv.y);
                mma16(acc[0][2 * jp + 1], a[0], bv.z, bv.w);
                mma16(acc[1][2 * jp + 1], a[1], bv.z, bv.w);
            }
        }
        __syncwarp();

        // ---- slice free: stage NEXT tile (overlaps epilogue) ----
        int tn = t + gridDim.x;
        if (tn < ntiles) {
            const int etn = tn * TILE + wb;
#pragma unroll
            for (int i = 0; i < 16; i++) {
                int g = lane + i * 32;
                int row = g >> 4, q = g & 15;
                int e = etn + row;
                float* d = &wsbuf[row * STRIDE + q * 4];
                if (e < E) cp16(d, rbf + (long)e * 64 + q * 4);
                else       *(float4*)d = make_float4(0.f, 0.f, 0.f, 0.f);
            }
            asm volatile("cp.async.commit_group;" ::: "memory");
        }

        // ---- epilogue from registers ----
#pragma unroll
        for (int mt = 0; mt < 2; mt++) {
#pragma unroll
            for (int rr = 0; rr < 2; rr++) {
                int x = mt * 16 + rr * 8 + r;
                int sN = __shfl_sync(0xffffffff, se, x);
                int dN = __shfl_sync(0xffffffff, de, x);
                if (et + x < E) {
                    const float* nr = nw + (long)sN * 64;
                    float* ob = out + (long)dN * 64;
#pragma unroll
                    for (int j = 0; j < 8; j++) {
                        int col = j * 8 + 2 * c;
                        float2 bb = *(const float2*)&B2S[col];
                        float2 nv = __ldg((const float2*)(nr + col));
                        red2(ob + col,
                             nv.x * (acc[mt][j][rr * 2 + 0] + bb.x),
                             nv.y * (acc[mt][j][rr * 2 + 1] + bb.y));
                    }
                }
            }
        }
    }
}

__global__ void zero_kernel(float4* __restrict__ o, int n4) {
    int i = blockIdx.x * blockDim.x + threadIdx.x;
    if (i < n4) o[i] = make_float4(0.f, 0.f, 0.f, 0.f);
}

extern "C" void kernel_launch(void* const* d_in, const int* in_sizes, int n_in,
                              void* d_out, int out_size) {
    const float* nw  = (const float*)d_in[0];
    const float* rbf = (const float*)d_in[1];
    const float* W1  = (const float*)d_in[2];
    const float* b1  = (const float*)d_in[3];
    const float* W2  = (const float*)d_in[4];
    const float* b2  = (const float*)d_in[5];
    const int*   src = (const int*)d_in[6];
    const int*   dst = (const int*)d_in[7];
    float* out = (float*)d_out;

    const int E = in_sizes[1] / 64;

    cudaFuncSetAttribute(cfconv_kernel,
                         cudaFuncAttributeMaxDynamicSharedMemorySize, SMEM_BYTES);

    int n4 = out_size / 4;
    zero_kernel<<<(n4 + 255) / 256, 256>>>((float4*)out, n4);

    cfconv_kernel<<<296, THREADS, SMEM_BYTES>>>(nw, rbf, W1, b1, W2, b2, src, dst, out, E);
}